// round 14
// baseline (speedup 1.0000x reference)
#include <cuda_runtime.h>
#include <cstdint>

#define BATCH   1024
#define WDIM    256
#define HDIM    256
#define DEPTH   8
#define HMAX    256     // absolute worst-case hull size
#define HP      12      // padded fast-path hull size (E[hull] ~ 6; P(>12) tiny)
#define NGRAN   (HP/2)  // 6 granules of 16B per w
#define NCTA    256     // 2 branches x 128 groups; co-resident at 2 CTAs/SM

#define F_INF   __int_as_float(0x7F800000)
#define F_NINF  __int_as_float(0xFF800000)

// Static device scratch (allocation-free rule).
__device__ float2 g_hull [2][DEPTH][WDIM][HMAX];   // oversized tail (k >= HP only)
__device__ float4 g_hullp[2][DEPTH][WDIM][NGRAN];  // 6 granules = 96B per w
__device__ int    g_cnt  [2][DEPTH][WDIM];
__device__ int    g_barA, g_barB;                  // zero-init; self-resetting

// Monotone float <-> uint key (uint order == float order, incl. +-inf).
__device__ __forceinline__ unsigned fkey(float f) {
    unsigned u = __float_as_uint(f);
    return (u & 0x80000000u) ? ~u : (u | 0x80000000u);
}
__device__ __forceinline__ float funkey(unsigned k) {
    unsigned u = (k & 0x80000000u) ? (k & 0x7FFFFFFFu) : ~k;
    return __uint_as_float(u);
}

#define CP_ASYNC16(dst, src) \
    asm volatile("cp.async.cg.shared.global [%0], [%1], 16;" :: "r"(dst), "l"(src))
#define CP_COMMIT() asm volatile("cp.async.commit_group;")
#define CP_WAIT(n)  asm volatile("cp.async.wait_group %0;" :: "n"(n))

// Packed f32x2 helpers (FFMA2 in SASS).
__device__ __forceinline__ uint64_t pack_dup(float f) {
    uint64_t r;
    asm("mov.b64 %0, {%1, %1};" : "=l"(r) : "f"(f));
    return r;
}
__device__ __forceinline__ void ffma2(uint64_t& d, uint64_t a, uint64_t b, uint64_t c) {
    asm("fma.rn.f32x2 %0, %1, %2, %3;" : "=l"(d) : "l"(a), "l"(b), "l"(c));
}
__device__ __forceinline__ void unpack2(float& lo, float& hi, uint64_t v) {
    asm("mov.b64 {%0, %1}, %2;" : "=f"(lo), "=f"(hi) : "l"(v));
}

// Write line k (k < HP) of a padded hull in granule layout (m0,m1,b0,b1).
__device__ __forceinline__ void store_line(float* hps, int k, float m, float b) {
    int g = k >> 1, o = k & 1;
    hps[g * 4 + o]     = m;
    hps[g * 4 + 2 + o] = b;
}

// One gift-wrapped upper envelope (warp-collective), R13-proven scan.
__device__ __forceinline__ void build_envelope(
    const float* __restrict__ M1, const float* __restrict__ B1,
    const float* __restrict__ M2, const float* __restrict__ B2,
    int gw, int lane) {
    const int branch = gw >> 11;
    const int d      = (gw >> 8) & 7;
    const int w      = gw & 255;

    const float* Mp = (branch ? M2 : M1) + (size_t)((d << 8) + w) * HDIM;
    const float* Bp = (branch ? B2 : B1) + (size_t)((d << 8) + w) * HDIM;

    float m[8], b[8];
    {
        const float4* M4 = (const float4*)Mp;
        const float4* B4 = (const float4*)Bp;
        float4 a0 = M4[lane * 2], a1 = M4[lane * 2 + 1];
        float4 c0 = B4[lane * 2], c1 = B4[lane * 2 + 1];
        m[0]=a0.x; m[1]=a0.y; m[2]=a0.z; m[3]=a0.w;
        m[4]=a1.x; m[5]=a1.y; m[6]=a1.z; m[7]=a1.w;
        b[0]=c0.x; b[1]=c0.y; b[2]=c0.z; b[3]=c0.w;
        b[4]=c1.x; b[5]=c1.y; b[6]=c1.z; b[7]=c1.w;
    }

    // Start line: min slope (dominated equal-slope start self-corrects).
    float mc = m[0], bc = b[0];
#pragma unroll
    for (int k = 1; k < 8; k++)
        if (m[k] < mc || (m[k] == mc && b[k] > bc)) { mc = m[k]; bc = b[k]; }
    {
        unsigned mk  = __reduce_min_sync(0xFFFFFFFFu, fkey(mc));
        unsigned bal = __ballot_sync(0xFFFFFFFFu, fkey(mc) == mk);
        int src = __ffs(bal) - 1;
        mc = __shfl_sync(0xFFFFFFFFu, mc, src);
        bc = __shfl_sync(0xFFFFFFFFu, bc, src);
    }

    float2* hf  = &g_hull[branch][d][w][0];
    float*  hps = (float*)&g_hullp[branch][d][w][0];
    const unsigned KEY_INF = fkey(F_INF);

    int cnt = 0;
    for (int step = 0; step < HMAX; ++step) {
        if (lane == 0) {
            if (cnt < HP) store_line(hps, cnt, mc, bc);
            else          hf[cnt] = make_float2(mc, bc);
        }
        cnt++;

        // Per-lane: smallest crossing x among overtaking lines.
        // dj==0 && nj<0 encodes x = -inf via fdividef (-/0 -> -inf).
        float bx = F_INF, bm = 0.f, bb = 0.f;
#pragma unroll
        for (int k = 0; k < 8; k++) {
            float dj = m[k] - mc;
            float nj = bc - b[k];
            bool valid = (dj > 0.f) || (dj == 0.f && nj < 0.f);
            float x = valid ? __fdividef(nj, dj) : F_INF;
            if (x < bx) { bx = x; bm = m[k]; bb = b[k]; }
        }
        unsigned wk = __reduce_min_sync(0xFFFFFFFFu, fkey(bx));
        if (wk >= KEY_INF) break;                     // envelope complete
        unsigned bal = __ballot_sync(0xFFFFFFFFu, fkey(bx) == wk);
        int src = __ffs(bal) - 1;
        mc = __shfl_sync(0xFFFFFFFFu, bm, src);
        bc = __shfl_sync(0xFFFFFFFFu, bb, src);
    }

    // Pad the compact hull with (0, -inf): neutral for max.
    for (int k = cnt + lane; k < HP; k += 32)
        store_line(hps, k, 0.f, F_NINF);
    if (lane == 0) g_cnt[branch][d][w] = cnt;
}

// ───────────────────────── fused kernel ─────────────────────────
// 256 CTAs x 512 threads, __launch_bounds__(512, 2): 64-reg cap, 2 CTAs/SM
// (smem 98.4KB x 2 = 197KB < 228KB carveout; 256 <= 2*148 -> all co-resident,
// so the counter grid-barrier cannot deadlock).
// Phase 1: 256 CTAs x 16 warps = 4096 warps -> EXACTLY one envelope per warp
//   (same parallelism as the standalone hull kernel; fixes R12's 2-round slowdown).
// Phase 2: R13 eval verbatim — branch x group-of-8, 2 q's + 2 w's per thread,
//   triple-buffered cp.async, FFMA2 dual accumulators, REDUX, 1 barrier/layer.
#define BUFS       32768
#define EVAL_SMEM  (3 * BUFS + 256)

__global__ void __launch_bounds__(512, 2)
fused_kernel(const float* __restrict__ M1, const float* __restrict__ B1,
             const float* __restrict__ M2, const float* __restrict__ B2,
             const float* __restrict__ val, float* __restrict__ out) {
    extern __shared__ char smem[];
    float2* s_red = (float2*)(smem + 3 * BUFS);     // [16 warps] = [4 pair][4 wblk]

    unsigned sbase;
    asm("{.reg .u64 t; cvta.to.shared.u64 t, %1; cvt.u32.u64 %0, t;}"
        : "=r"(sbase) : "l"(smem));

    const int t    = threadIdx.x;
    const int warp = t >> 5;
    const int lane = t & 31;

    // ── Phase 1: one envelope per warp (full hull parallelism) ──
    build_envelope(M1, B1, M2, B2, blockIdx.x * 16 + warp, lane);

    // ── Grid barrier: all hulls published before any staging ──
    __syncthreads();
    if (t == 0) {
        __threadfence();                           // release this CTA's hulls
        atomicAdd(&g_barA, 1);
        while (*(volatile int*)&g_barA < NCTA) __nanosleep(32);
        __threadfence();                           // acquire everyone's hulls
    }
    __syncthreads();

    // ── Phase 2: eval (R13 shape) ──
    const int branch = blockIdx.x >> 7;
    const int grp8   = blockIdx.x & 127;          // group of 8 batches
    const int pair   = t >> 7;                    // 0..3 -> batches pair*2, +1
    const int wsub   = t & 127;                   // w0 = wsub, w1 = wsub + 128

    float q[2];
#pragma unroll
    for (int i = 0; i < 2; i++) q[i] = val[grp8 * 8 + pair * 2 + i];

    // Pre-stage layers 0 and 1: 1536 float4 per layer, 3 per thread.
#pragma unroll
    for (int L = 0; L < 2; L++) {
        const float4* src = &g_hullp[branch][L][0][0];
#pragma unroll
        for (int k = 0; k < 3; k++) {
            int n = t + (k << 9);                 // 0..1535
            int w = n / NGRAN, g = n % NGRAN;
            unsigned dst = sbase + (unsigned)(L * BUFS + w * 128 + ((g ^ (w & 7)) << 4));
            CP_ASYNC16(dst, src + n);
        }
        CP_COMMIT();
    }

    for (int d = 0; d < DEPTH; ++d) {
        if (d < DEPTH - 1) CP_WAIT(1); else CP_WAIT(0);
        __syncthreads();   // layer-d staged; s_red[d-1] visible; buf (d+2)%3 free

        if (d > 0) {       // rebuild q: min over the 4 wblk partials (broadcast)
            float2 r0 = s_red[pair * 4 + 0];
            float2 r1 = s_red[pair * 4 + 1];
            float2 r2 = s_red[pair * 4 + 2];
            float2 r3 = s_red[pair * 4 + 3];
            q[0] = fminf(fminf(r0.x, r1.x), fminf(r2.x, r3.x));
            q[1] = fminf(fminf(r0.y, r1.y), fminf(r2.y, r3.y));
        }
        uint64_t q2[2];
#pragma unroll
        for (int i = 0; i < 2; i++) q2[i] = pack_dup(q[i]);

        if (d + 2 < DEPTH) {                      // prefetch layer d+2
            const float4* src = &g_hullp[branch][d + 2][0][0];
            unsigned bufo = (unsigned)(((d + 2) % 3) * BUFS);
#pragma unroll
            for (int k = 0; k < 3; k++) {
                int n = t + (k << 9);
                int w = n / NGRAN, g = n % NGRAN;
                unsigned dst = sbase + bufo + (unsigned)(w * 128 + ((g ^ (w & 7)) << 4));
                CP_ASYNC16(dst, src + n);
            }
            CP_COMMIT();
        }

        const char* hb = smem + (d % 3) * BUFS;
        int cw0 = g_cnt[branch][d][wsub];
        int cw1 = g_cnt[branch][d][wsub + 128];

        float vmin[2] = {F_INF, F_INF};
#pragma unroll
        for (int wo = 0; wo < 2; wo++) {
            const int w  = wsub + wo * 128;
            const int cw = wo ? cw1 : cw0;
            const char* hw = hb + w * 128;
            const int ws7 = w & 7;

            // Dual accumulators per q; two granule batches of 3 (fits 64 regs).
            float va[2] = {F_NINF, F_NINF};
            float vb[2] = {F_NINF, F_NINF};
#pragma unroll
            for (int half = 0; half < 2; half++) {
                ulonglong2 P[3];
#pragma unroll
                for (int g = 0; g < 3; g++)
                    P[g] = *(const ulonglong2*)(hw + (((half * 3 + g) ^ ws7) << 4));
#pragma unroll
                for (int g = 0; g < 3; g++) {
#pragma unroll
                    for (int i = 0; i < 2; i++) {
                        uint64_t s;
                        ffma2(s, q2[i], P[g].x, P[g].y);
                        float lo, hi;
                        unpack2(lo, hi, s);
                        va[i] = fmaxf(va[i], lo);
                        vb[i] = fmaxf(vb[i], hi);
                    }
                }
            }
            float vmax[2];
#pragma unroll
            for (int i = 0; i < 2; i++) vmax[i] = fmaxf(va[i], vb[i]);

            // Oversized hulls: warp-uniform gate; tail folds into vmax BEFORE min.
            if (__reduce_max_sync(0xFFFFFFFFu, (unsigned)cw) > HP) {
                if (cw > HP) {
                    const float2* fp = &g_hull[branch][d][w][0];
                    for (int k = HP; k < cw; k++) {
                        float2 l2 = __ldg(fp + k);
#pragma unroll
                        for (int i = 0; i < 2; i++)
                            vmax[i] = fmaxf(vmax[i], fmaf(q[i], l2.x, l2.y));
                    }
                }
            }
#pragma unroll
            for (int i = 0; i < 2; i++) vmin[i] = fminf(vmin[i], vmax[i]);
        }

        // Warp-wide min over this warp's 64 w's (all lanes share the pair).
#pragma unroll
        for (int i = 0; i < 2; i++)
            vmin[i] = funkey(__reduce_min_sync(0xFFFFFFFFu, fkey(vmin[i])));
        if (lane == 0) s_red[warp] = make_float2(vmin[0], vmin[1]);
        // Published by next layer's barrier.
    }

    __syncthreads();
    if (t < 8) {
        const int pp = t >> 1, ii = t & 1;
        float acc = F_INF;
#pragma unroll
        for (int wb = 0; wb < 4; wb++) {
            float2 r = s_red[pp * 4 + wb];
            acc = fminf(acc, ii ? r.y : r.x);
        }
        out[branch * BATCH + grp8 * 8 + t] = acc;
    }

    // Self-resetting barrier counters: the LAST CTA here knows every other CTA
    // has passed its spin loop -> safe to zero both for the next graph replay.
    if (t == 0) {
        int pos = atomicAdd(&g_barB, 1);
        if (pos == NCTA - 1) {
            *(volatile int*)&g_barA = 0;
            *(volatile int*)&g_barB = 0;
            __threadfence();
        }
    }
}

extern "C" void kernel_launch(void* const* d_in, const int* in_sizes, int n_in,
                              void* d_out, int out_size) {
    const float* val = (const float*)d_in[0];
    const float* M1  = (const float*)d_in[1];
    const float* B1  = (const float*)d_in[2];
    const float* M2  = (const float*)d_in[3];
    const float* B2  = (const float*)d_in[4];
    float* out = (float*)d_out;

    cudaFuncSetAttribute(fused_kernel,
                         cudaFuncAttributeMaxDynamicSharedMemorySize, EVAL_SMEM);

    fused_kernel<<<NCTA, 512, EVAL_SMEM>>>(M1, B1, M2, B2, val, out);
}

// round 15
// speedup vs baseline: 1.1104x; 1.1104x over previous
#include <cuda_runtime.h>
#include <cstdint>

#define BATCH   1024
#define WDIM    256
#define HDIM    256
#define DEPTH   8
#define HMAX    256     // absolute worst-case hull size
#define HP      12      // padded fast-path hull size
#define NGRAN   (HP/2)  // 6 granules of 16B per w

#define F_INF   __int_as_float(0x7F800000)
#define F_NINF  __int_as_float(0xFF800000)

// Static device scratch (allocation-free rule).
// Transposed padded hulls: granule-major so warp-lane-consecutive w gives
// perfectly coalesced LDG.128. Granule g of w holds lines 2g,2g+1 as
// (m0, m1, b0, b1).
__device__ float2 g_hull  [2][DEPTH][WDIM][HMAX];   // oversized tail (k >= HP)
__device__ float4 g_hullpT[2][DEPTH][NGRAN][WDIM];  // 16B granule per (g, w)
__device__ int    g_cnt   [2][DEPTH][WDIM];

// Monotone float <-> uint key (uint order == float order, incl. +-inf).
__device__ __forceinline__ unsigned fkey(float f) {
    unsigned u = __float_as_uint(f);
    return (u & 0x80000000u) ? ~u : (u | 0x80000000u);
}
__device__ __forceinline__ float funkey(unsigned k) {
    unsigned u = (k & 0x80000000u) ? (k & 0x7FFFFFFFu) : ~k;
    return __uint_as_float(u);
}

// Packed f32x2 helpers (FFMA2 in SASS).
__device__ __forceinline__ uint64_t pack_dup(float f) {
    uint64_t r;
    asm("mov.b64 %0, {%1, %1};" : "=l"(r) : "f"(f));
    return r;
}
__device__ __forceinline__ void ffma2(uint64_t& d, uint64_t a, uint64_t b, uint64_t c) {
    asm("fma.rn.f32x2 %0, %1, %2, %3;" : "=l"(d) : "l"(a), "l"(b), "l"(c));
}
__device__ __forceinline__ void unpack2(float& lo, float& hi, uint64_t v) {
    asm("mov.b64 {%0, %1}, %2;" : "=f"(lo), "=f"(hi) : "l"(v));
}

// Write line k (k < HP) of w's padded hull in the TRANSPOSED layout.
__device__ __forceinline__ void store_line_T(float4* hbT, int w, int k,
                                             float m, float b) {
    int g = k >> 1, o = k & 1;
    float* c = (float*)(hbT + g * WDIM + w);
    c[o]     = m;
    c[2 + o] = b;
}

// ───────────────────────── hull kernel ─────────────────────────
// One warp per envelope (branch, d, w); 512 CTAs x 256 thr (max warp count;
// hull is per-step latency bound). Proven R13 scan, transposed output.
__global__ void __launch_bounds__(256) hull_kernel(
    const float* __restrict__ M1, const float* __restrict__ B1,
    const float* __restrict__ M2, const float* __restrict__ B2) {
    const int gw     = (blockIdx.x * blockDim.x + threadIdx.x) >> 5;  // 0..4095
    const int lane   = threadIdx.x & 31;
    const int branch = gw >> 11;
    const int d      = (gw >> 8) & 7;
    const int w      = gw & 255;

    const float* Mp = (branch ? M2 : M1) + (size_t)((d << 8) + w) * HDIM;
    const float* Bp = (branch ? B2 : B1) + (size_t)((d << 8) + w) * HDIM;

    float m[8], b[8];
    {
        const float4* M4 = (const float4*)Mp;
        const float4* B4 = (const float4*)Bp;
        float4 a0 = M4[lane * 2], a1 = M4[lane * 2 + 1];
        float4 c0 = B4[lane * 2], c1 = B4[lane * 2 + 1];
        m[0]=a0.x; m[1]=a0.y; m[2]=a0.z; m[3]=a0.w;
        m[4]=a1.x; m[5]=a1.y; m[6]=a1.z; m[7]=a1.w;
        b[0]=c0.x; b[1]=c0.y; b[2]=c0.z; b[3]=c0.w;
        b[4]=c1.x; b[5]=c1.y; b[6]=c1.z; b[7]=c1.w;
    }

    // Start line: min slope (dominated equal-slope start self-corrects).
    float mc = m[0], bc = b[0];
#pragma unroll
    for (int k = 1; k < 8; k++)
        if (m[k] < mc || (m[k] == mc && b[k] > bc)) { mc = m[k]; bc = b[k]; }
    {
        unsigned mk  = __reduce_min_sync(0xFFFFFFFFu, fkey(mc));
        unsigned bal = __ballot_sync(0xFFFFFFFFu, fkey(mc) == mk);
        int src = __ffs(bal) - 1;
        mc = __shfl_sync(0xFFFFFFFFu, mc, src);
        bc = __shfl_sync(0xFFFFFFFFu, bc, src);
    }

    float2* hf  = &g_hull[branch][d][w][0];
    float4* hbT = &g_hullpT[branch][d][0][0];
    const unsigned KEY_INF = fkey(F_INF);

    int cnt = 0;
    for (int step = 0; step < HMAX; ++step) {
        if (lane == 0) {
            if (cnt < HP) store_line_T(hbT, w, cnt, mc, bc);
            else          hf[cnt] = make_float2(mc, bc);
        }
        cnt++;

        // Per-lane: smallest crossing x among overtaking lines.
        // dj==0 && nj<0 encodes x = -inf via fdividef (-/0 -> -inf).
        float bx = F_INF, bm = 0.f, bb = 0.f;
#pragma unroll
        for (int k = 0; k < 8; k++) {
            float dj = m[k] - mc;
            float nj = bc - b[k];
            bool valid = (dj > 0.f) || (dj == 0.f && nj < 0.f);
            float x = valid ? __fdividef(nj, dj) : F_INF;
            if (x < bx) { bx = x; bm = m[k]; bb = b[k]; }
        }
        unsigned wk = __reduce_min_sync(0xFFFFFFFFu, fkey(bx));
        if (wk >= KEY_INF) break;                     // envelope complete
        unsigned bal = __ballot_sync(0xFFFFFFFFu, fkey(bx) == wk);
        int src = __ffs(bal) - 1;
        mc = __shfl_sync(0xFFFFFFFFu, bm, src);
        bc = __shfl_sync(0xFFFFFFFFu, bb, src);
    }

    // Pad the compact hull with (0, -inf): neutral for max.
    for (int k = cnt + lane; k < HP; k += 32)
        store_line_T(hbT, w, k, 0.f, F_NINF);
    if (lane == 0) g_cnt[branch][d][w] = cnt;
}

// ───────────────────────── eval kernel ─────────────────────────
// 256 CTAs: bid = branch (bx>>7) x batch-group-of-8 (bx&127). 512 threads,
// __launch_bounds__(512,2) -> 64-reg cap, 2 CTAs/SM (smem is only 512B now).
// Thread map: duo = t>>8 (owns 4 batches), w = t&255 (ONE w per thread).
// NO smem staging: granules loaded straight from the transposed global array
// (coalesced LDG.128, L1-resident). Reductions in KEY domain: fkey once,
// REDUX.U32 over the warp's 32 w's, keys in s_red, integer-min rebuild.
// s_red double-buffered by layer parity -> no read/write race across warps.
__global__ void __launch_bounds__(512, 2) eval_kernel(
    const float* __restrict__ val, float* __restrict__ out) {
    __shared__ uint4 s_red[2][16];   // [layer parity][duo*8 + wblk]

    const int t      = threadIdx.x;
    const int branch = blockIdx.x >> 7;
    const int grp8   = blockIdx.x & 127;
    const int warp   = t >> 5;
    const int lane   = t & 31;
    const int duo    = t >> 8;                   // 0..1 -> batches duo*4 .. +3
    const int w      = t & 255;                  // this thread's w, all layers

    float    qf[4];
    uint64_t q2[4];
#pragma unroll
    for (int i = 0; i < 4; i++) {
        qf[i] = val[grp8 * 8 + duo * 4 + i];
        q2[i] = pack_dup(qf[i]);
    }

    const ulonglong2* hb = (const ulonglong2*)&g_hullpT[branch][0][0][w];
    const int*        cp = &g_cnt[branch][0][w];

    for (int d = 0; d < DEPTH; ++d) {
        if (d > 0) {
            // Rebuild q: keys from the 8 wblk partials of my duo.
            // Lane j holds partial (j&7); 3-round xor-shfl integer-min tree.
            uint4 r = s_red[(d - 1) & 1][duo * 8 + (lane & 7)];
#pragma unroll
            for (int off = 1; off <= 4; off <<= 1) {
                r.x = min(r.x, __shfl_xor_sync(0xFFFFFFFFu, r.x, off));
                r.y = min(r.y, __shfl_xor_sync(0xFFFFFFFFu, r.y, off));
                r.z = min(r.z, __shfl_xor_sync(0xFFFFFFFFu, r.z, off));
                r.w = min(r.w, __shfl_xor_sync(0xFFFFFFFFu, r.w, off));
            }
            qf[0] = funkey(r.x); qf[1] = funkey(r.y);
            qf[2] = funkey(r.z); qf[3] = funkey(r.w);
#pragma unroll
            for (int i = 0; i < 4; i++) q2[i] = pack_dup(qf[i]);
        }

        // Batch all 6 granules (MLP=6, coalesced, L1-resident).
        ulonglong2 P[NGRAN];
#pragma unroll
        for (int g = 0; g < NGRAN; g++)
            P[g] = __ldg(hb + g * WDIM);

        // Dual accumulators per q: two FMNMX chains of 6.
        float va[4] = {F_NINF, F_NINF, F_NINF, F_NINF};
        float vb[4] = {F_NINF, F_NINF, F_NINF, F_NINF};
#pragma unroll
        for (int g = 0; g < NGRAN; g++) {
#pragma unroll
            for (int i = 0; i < 4; i++) {
                uint64_t s;
                ffma2(s, q2[i], P[g].x, P[g].y);   // lines 2g, 2g+1 at q[i]
                float lo, hi;
                unpack2(lo, hi, s);
                va[i] = fmaxf(va[i], lo);
                vb[i] = fmaxf(vb[i], hi);
            }
        }
        float vmax[4];
#pragma unroll
        for (int i = 0; i < 4; i++) vmax[i] = fmaxf(va[i], vb[i]);

        // Oversized hulls: warp-uniform gate; tail folds into vmax BEFORE min.
        int cw = __ldg(cp);
        if (__reduce_max_sync(0xFFFFFFFFu, (unsigned)cw) > HP) {
            if (cw > HP) {
                const float2* fp = &g_hull[branch][d][w][0];
                for (int k = HP; k < cw; k++) {
                    float2 l2 = __ldg(fp + k);
#pragma unroll
                    for (int i = 0; i < 4; i++)
                        vmax[i] = fmaxf(vmax[i], fmaf(qf[i], l2.x, l2.y));
                }
            }
        }

        // Warp-wide min over this warp's 32 w's, in key domain.
        uint4 kk;
        kk.x = __reduce_min_sync(0xFFFFFFFFu, fkey(vmax[0]));
        kk.y = __reduce_min_sync(0xFFFFFFFFu, fkey(vmax[1]));
        kk.z = __reduce_min_sync(0xFFFFFFFFu, fkey(vmax[2]));
        kk.w = __reduce_min_sync(0xFFFFFFFFu, fkey(vmax[3]));
        if (lane == 0) s_red[d & 1][duo * 8 + (warp & 7)] = kk;
        __syncthreads();   // publish partials; separates parity banks

        hb += NGRAN * WDIM;   // next layer (16B units match float4 layout)
        cp += WDIM;
    }

    // Final combine: min over the 8 wblk partials of each duo, key domain.
    if (t < 8) {
        const int dd = t >> 2, ii = t & 3;
        unsigned acc = 0xFFFFFFFFu;
#pragma unroll
        for (int wb = 0; wb < 8; wb++) {
            uint4 r = s_red[(DEPTH - 1) & 1][dd * 8 + wb];
            unsigned v = (ii == 0) ? r.x : (ii == 1) ? r.y : (ii == 2) ? r.z : r.w;
            acc = min(acc, v);
        }
        out[branch * BATCH + grp8 * 8 + t] = funkey(acc);
    }
}

extern "C" void kernel_launch(void* const* d_in, const int* in_sizes, int n_in,
                              void* d_out, int out_size) {
    const float* val = (const float*)d_in[0];
    const float* M1  = (const float*)d_in[1];
    const float* B1  = (const float*)d_in[2];
    const float* M2  = (const float*)d_in[3];
    const float* B2  = (const float*)d_in[4];
    float* out = (float*)d_out;

    hull_kernel<<<(2 * DEPTH * WDIM) / 8, 256>>>(M1, B1, M2, B2);
    eval_kernel<<<256, 512>>>(val, out);
}